// round 8
// baseline (speedup 1.0000x reference)
#include <cuda_runtime.h>
#include <math.h>

#define BIMG 4
#define HP   74
#define IMGPIX 6400
#define BT   640

// 1 / (49 * sqrt(2*pi*2.5^2))
#define KDE_SCALE 3.2566726960192768e-03f
// -ln2 / 49
#define NEG_LN2_49 (-1.4145860827753985e-02f)

// shared floats: xs[960] | dvi[640](int) | S[2*7280] | L[2*3920] | red[640] | lut[512]
#define F_XS   0
#define F_DVI  960
#define F_S    1600
#define F_L    16160
#define F_RED  24000
#define F_LUT  24640
#define SMEM_BYTES ((24640 + 512) * 4)

// ---------------------------------------------------------------------------
// One block per (band pair g, image b): output rows py0+3, py0+4 (py0 = 2g).
//  1) zero S, load 12 input rows (float4), build 511-entry exp LUT
//  2) blur/round -> sharp -> division (exact op order), stored as int
//  3) KDE column sums for both bands: exp = LDS from LUT[d+255]; marginal
//     accumulation (U/V) + boundary corrections
//  4) prefix over dc -> window sums -> log2 -> L
//  5) entropy per window (4 threads each), deterministic combine; borders
// ---------------------------------------------------------------------------
__global__ __launch_bounds__(BT, 1)
void entropy_pair_kernel(const float* __restrict__ x, float* __restrict__ out) {
    extern __shared__ float sm[];
    float* xs   = sm + F_XS;
    int*   dvi  = (int*)(sm + F_DVI);   // integer division values
    float* S    = sm + F_S;             // [band][(r*80+xp)*13 + dc]
    float* L    = sm + F_L;             // [band][(r*7+c)*80 + xp]
    float* red  = sm + F_RED;
    float* lutf = sm + F_LUT;           // lut[i] = exp(-(i-255)^2 * 0.08)

    const int tid = threadIdx.x;
    const int g   = blockIdx.x;        // 0..36
    const int b   = blockIdx.y;        // 0..3
    const int py0 = 2 * g;
    const float* img = x + b * IMGPIX;
    float* ob = out + b * IMGPIX;

    // -- 1: zero S + load input rows + build LUT ------------------------------
    {
        float4* S4 = (float4*)S;
        for (int i = tid; i < 14560 / 4; i += BT)
            S4[i] = make_float4(0.f, 0.f, 0.f, 0.f);
    }
    {
        float4* xs4 = (float4*)xs;
        const float4* img4 = (const float4*)img;
        for (int i = tid; i < 240; i += BT) {     // 12 rows * 20 float4
            int r = i / 20, c4 = i - r * 20;
            int row = py0 - 2 + r;
            xs4[i] = ((unsigned)row < 80u) ? img4[row * 20 + c4]
                                           : make_float4(0.f, 0.f, 0.f, 0.f);
        }
    }
    if (tid < 511) {
        float d  = (float)(tid - 255);
        float d2 = d * d;                          // exact integer in fp32
        lutf[tid] = __expf(d2 * -0.08f);           // exp(-d^2 / (2*2.5^2))
    }
    __syncthreads();

    // -- 2: preprocessing (exact op order); store integer --------------------
    {
        int r = tid / 80, c = tid - (tid / 80) * 80;   // r = 0..7
        float sum = 0.0f;
        #pragma unroll
        for (int dy = 0; dy < 5; dy++) {
            const float* rowp = xs + (r + dy) * 80;
            #pragma unroll
            for (int dx = -2; dx <= 2; dx++) {
                int cc = c + dx;
                if ((unsigned)cc < 80u) sum = __fadd_rn(sum, rowp[cc]);
            }
        }
        float smooth = rintf(__fdiv_rn(sum, 25.0f));
        float cv     = xs[(r + 2) * 80 + c];
        float sharp  = rintf(fminf(fmaxf(
                          __fsub_rn(__fmul_rn(2.5f, cv), __fmul_rn(1.25f, smooth)),
                          0.0f), 255.0f));
        float divi   = rintf(fminf(fmaxf(
                          __fdiv_rn(__fmul_rn(sharp, 255.0f),
                                    __fadd_rn(smooth, 1e-8f)),
                          0.0f), 255.0f));
        dvi[tid] = (int)divi;
    }
    __syncthreads();

    // -- 3: shared KDE column sums for both bands (LUT exp + marginals) ------
    if (tid < 560) {
        int dc = tid / 80;             // 0..6
        int xp = tid - dc * 80;        // 0..79
        int xc = xp - 6 + dc;          // <= xp
        if (xc >= 0) {
            int iA[8], iB[8];
            #pragma unroll
            for (int a = 0; a < 8; a++) {
                iA[a] = dvi[a * 80 + xp] + 255;
                iB[a] = dvi[a * 80 + xc];
            }
            float U[8], V[8];
            #pragma unroll
            for (int a = 0; a < 8; a++) { U[a] = 0.f; V[a] = 0.f; }
            float eA7[7], eA0[8], eB0[8], eB7[7];   // boundary exps
            #pragma unroll
            for (int bb = 0; bb < 8; bb++) {
                int ib = iB[bb];
                #pragma unroll
                for (int a = 0; a < 8; a++) {
                    float e = lutf[iA[a] - ib];
                    U[a]  += e;
                    V[bb] += e;
                    if (bb == 7 && a < 7) eA7[a] = e;
                    if (bb == 0 && a > 0) eA0[a] = e;
                    if (a == 0 && bb > 0) eB0[bb] = e;
                    if (a == 7 && bb < 7) eB7[bb] = e;
                }
            }
            #pragma unroll
            for (int r = 0; r < 7; r++) {
                S[(r * 80 + xp) * 13 + dc]        = U[r]     - eA7[r];     // s0
                S[7280 + (r * 80 + xp) * 13 + dc] = U[r + 1] - eA0[r + 1]; // s1
            }
            if (dc < 6) {              // mirror: column xc, offset 12-dc
                #pragma unroll
                for (int r = 0; r < 7; r++) {
                    S[(r * 80 + xc) * 13 + (12 - dc)]        = V[r]     - eB7[r];     // t0
                    S[7280 + (r * 80 + xc) * 13 + (12 - dc)] = V[r + 1] - eB0[r + 1]; // t1
                }
            }
        }
    }
    __syncthreads();

    // -- 4: window sums via prefix, then log2 --------------------------------
    for (int it = tid; it < 1120; it += BT) {
        int h  = it / 560;
        int rr = it - h * 560;         // r*80 + xp
        const float* Sp = S + h * 7280 + rr * 13;
        float pref[14];
        pref[0] = 0.0f;
        #pragma unroll
        for (int k = 0; k < 13; k++) pref[k + 1] = pref[k] + Sp[k];
        int r = rr / 80, xp = rr - (rr / 80) * 80;
        float* Lh = L + h * 3920;
        #pragma unroll
        for (int c = 0; c < 7; c++) {
            float W = pref[13 - c] - pref[6 - c];   // >= 1 for valid windows
            Lh[(r * 7 + c) * 80 + xp] = __log2f(fmaf(W, KDE_SCALE, 1e-8f));
        }
    }
    __syncthreads();

    // -- 5: entropy per window (4 threads each), deterministic combine -------
    {
        float acc = 0.0f;
        if (tid < 592) {
            int w    = tid >> 2;               // 0..147
            int part = tid & 3;
            int h    = w / 74;
            int xw   = w - h * 74;
            const float* Lh = L + h * 3920;
            int i0 = part * 13;
            int i1 = (part == 3) ? 49 : i0 + 13;
            int r = i0 / 7, c = i0 - (i0 / 7) * 7;
            for (int i = i0; i < i1; i++) {
                acc += Lh[(r * 7 + c) * 80 + xw + c];
                if (++c == 7) { c = 0; r++; }
            }
        }
        red[tid] = acc;
    }
    __syncthreads();

    if (tid < 148) {
        int h  = tid / 74;
        int xw = tid - h * 74;
        float tot = red[tid * 4] + red[tid * 4 + 1]
                  + red[tid * 4 + 2] + red[tid * 4 + 3];
        ob[(py0 + h + 3) * 80 + (xw + 3)] = tot * NEG_LN2_49;
    }
    // column borders of the two written rows
    if (tid >= 160 && tid < 172) {
        int k = tid - 160;
        int h = k / 6, j = k - h * 6;
        int col = (j < 3) ? j : (74 + j);      // 0,1,2,77,78,79
        ob[(py0 + h + 3) * 80 + col] = 0.0f;
    }
    // top / bottom border rows
    if (g == 0  && tid < 240) ob[tid] = 0.0f;             // rows 0..2
    if (g == 36 && tid < 240) ob[77 * 80 + tid] = 0.0f;   // rows 77..79
}

// ---------------------------------------------------------------------------
extern "C" void kernel_launch(void* const* d_in, const int* in_sizes, int n_in,
                              void* d_out, int out_size) {
    const float* x = (const float*)d_in[0];
    float* out     = (float*)d_out;

    cudaFuncSetAttribute(entropy_pair_kernel,
                         cudaFuncAttributeMaxDynamicSharedMemorySize, SMEM_BYTES);
    dim3 grid(37, BIMG);               // 148 blocks = 1 per SM
    entropy_pair_kernel<<<grid, BT, SMEM_BYTES>>>(x, out);
}

// round 9
// speedup vs baseline: 1.4815x; 1.4815x over previous
#include <cuda_runtime.h>
#include <math.h>

#define BIMG 4
#define HP   74
#define IMGPIX 6400
#define BT   640

// sqrt(log2(e) / (2*2.5^2)): arg = -(d*S)^2 == d^2 * NEG_C2
#define SCALE_S 0.33972874f
// -ln2 / 49
#define NEG_LN2_49 (-1.4145860827753985e-02f)
// ln(49 * sqrt(2*pi*2.5^2)) : folds the dropped per-element scale back in
#define ENT_OFF 5.7270496f

// shared floats: xs[12*80] | dvs[8*80] | S[2*7280] | L(=W)[2*3920] | red[640]
#define F_XS  0
#define F_DV  960
#define F_S   1600
#define F_L   16160
#define F_RED 24000
#define SMEM_BYTES ((24000 + 640) * 4)

__device__ __forceinline__ float ex2f(float x) {
    float y;
    asm("ex2.approx.f32 %0, %1;" : "=f"(y) : "f"(x));
    return y;
}
__device__ __forceinline__ float lg2f(float x) {
    float y;
    asm("lg2.approx.f32 %0, %1;" : "=f"(y) : "f"(x));
    return y;
}

// ---------------------------------------------------------------------------
// One block per (band pair g, image b): output rows py0+3, py0+4 (py0 = 2g).
//  1) load 12 input rows (float4, issued first), zero S
//  2) blur/round -> sharp -> division (exact op order), stored PRE-SCALED
//  3) KDE column sums for both bands via 8x8 row-pair exps, marginal
//     accumulation (U/V) + boundary corrections
//  4) prefix over dc -> 7 raw window sums W per (band,r,xp)  (NO logs)
//  5) per window: 4 partial PRODUCTS of W (13/12/12/12 terms), then only
//     4 lg2 per window:  ent = -ln2/49 * sum(lg2 Pk) + ENT_OFF
// ---------------------------------------------------------------------------
__global__ __launch_bounds__(BT, 1)
void entropy_pair_kernel(const float* __restrict__ x, float* __restrict__ out) {
    extern __shared__ float sm[];
    float* xs  = sm + F_XS;
    float* dvs = sm + F_DV;    // pre-scaled division values
    float* S   = sm + F_S;     // [band][(r*80+xp)*13 + dc]
    float* L   = sm + F_L;     // raw W: [band][(r*7+c)*80 + xp]
    float* red = sm + F_RED;

    const int tid = threadIdx.x;
    const int g   = blockIdx.x;        // 0..36
    const int b   = blockIdx.y;        // 0..3
    const int py0 = 2 * g;
    const float* img = x + b * IMGPIX;
    float* ob = out + b * IMGPIX;

    // -- 1: input loads first (hide DRAM latency), then zero S ---------------
    {
        float4* xs4 = (float4*)xs;
        const float4* img4 = (const float4*)img;
        for (int i = tid; i < 240; i += BT) {     // 12 rows * 20 float4
            int r = i / 20, c4 = i - r * 20;
            int row = py0 - 2 + r;
            xs4[i] = ((unsigned)row < 80u) ? img4[row * 20 + c4]
                                           : make_float4(0.f, 0.f, 0.f, 0.f);
        }
    }
    {
        float4* S4 = (float4*)S;
        for (int i = tid; i < 14560 / 4; i += BT)
            S4[i] = make_float4(0.f, 0.f, 0.f, 0.f);
    }
    __syncthreads();

    // -- 2: preprocessing (exact op order); store scaled ---------------------
    {
        int r = tid / 80, c = tid - (tid / 80) * 80;   // r = 0..7
        float sum = 0.0f;
        #pragma unroll
        for (int dy = 0; dy < 5; dy++) {
            const float* rowp = xs + (r + dy) * 80;
            #pragma unroll
            for (int dx = -2; dx <= 2; dx++) {
                int cc = c + dx;
                if ((unsigned)cc < 80u) sum = __fadd_rn(sum, rowp[cc]);
            }
        }
        float smooth = rintf(__fdiv_rn(sum, 25.0f));
        float cv     = xs[(r + 2) * 80 + c];
        float sharp  = rintf(fminf(fmaxf(
                          __fsub_rn(__fmul_rn(2.5f, cv), __fmul_rn(1.25f, smooth)),
                          0.0f), 255.0f));
        float divi   = rintf(fminf(fmaxf(
                          __fdiv_rn(__fmul_rn(sharp, 255.0f),
                                    __fadd_rn(smooth, 1e-8f)),
                          0.0f), 255.0f));
        dvs[tid] = __fmul_rn(divi, SCALE_S);
    }
    __syncthreads();

    // -- 3: shared KDE column sums for both bands (marginal accumulation) ----
    if (tid < 560) {
        int dc = tid / 80;             // 0..6
        int xp = tid - dc * 80;        // 0..79
        int xc = xp - 6 + dc;          // <= xp
        if (xc >= 0) {
            float vA[8];
            #pragma unroll
            for (int a = 0; a < 8; a++) vA[a] = dvs[a * 80 + xp];
            float U[8], V[8];
            #pragma unroll
            for (int a = 0; a < 8; a++) { U[a] = 0.f; V[a] = 0.f; }
            float eA7[7], eA0[8], eB0[8], eB7[7];   // boundary exps
            #pragma unroll
            for (int bb = 0; bb < 8; bb++) {
                float vb = dvs[bb * 80 + xc];
                #pragma unroll
                for (int a = 0; a < 8; a++) {
                    float d = vA[a] - vb;
                    float e = ex2f(d * (-d));       // = exp2(-(d')^2)
                    U[a]  += e;
                    V[bb] += e;
                    if (bb == 7 && a < 7) eA7[a] = e;
                    if (bb == 0 && a > 0) eA0[a] = e;
                    if (a == 0 && bb > 0) eB0[bb] = e;
                    if (a == 7 && bb < 7) eB7[bb] = e;
                }
            }
            #pragma unroll
            for (int r = 0; r < 7; r++) {
                S[(r * 80 + xp) * 13 + dc]        = U[r]     - eA7[r];     // s0
                S[7280 + (r * 80 + xp) * 13 + dc] = U[r + 1] - eA0[r + 1]; // s1
            }
            if (dc < 6) {              // mirror: column xc, offset 12-dc
                #pragma unroll
                for (int r = 0; r < 7; r++) {
                    S[(r * 80 + xc) * 13 + (12 - dc)]        = V[r]     - eB7[r];     // t0
                    S[7280 + (r * 80 + xc) * 13 + (12 - dc)] = V[r + 1] - eB0[r + 1]; // t1
                }
            }
        }
    }
    __syncthreads();

    // -- 4: raw window sums via prefix (no logs, no scale) -------------------
    for (int it = tid; it < 1120; it += BT) {
        int h  = it / 560;
        int rr = it - h * 560;         // r*80 + xp
        const float* Sp = S + h * 7280 + rr * 13;
        float pref[14];
        pref[0] = 0.0f;
        #pragma unroll
        for (int k = 0; k < 13; k++) pref[k + 1] = pref[k] + Sp[k];
        int r = rr / 80, xp = rr - (rr / 80) * 80;
        float* Lh = L + h * 3920;
        #pragma unroll
        for (int c = 0; c < 7; c++)
            Lh[(r * 7 + c) * 80 + xp] = pref[13 - c] - pref[6 - c];  // W >= 1
    }
    __syncthreads();

    // -- 5: partial products per window (4 threads each), 4 lg2 at the end ---
    {
        float acc = 1.0f;
        if (tid < 592) {
            int w    = tid >> 2;               // 0..147
            int part = tid & 3;
            int h    = w / 74;
            int xw   = w - h * 74;
            const float* Lh = L + h * 3920;
            int i0 = (part == 0) ? 0 : (13 + 12 * (part - 1));
            int i1 = (part == 0) ? 13 : (i0 + 12);
            int r = i0 / 7, c = i0 - (i0 / 7) * 7;
            for (int i = i0; i < i1; i++) {
                acc *= Lh[(r * 7 + c) * 80 + xw + c];   // product <= 49^13
                if (++c == 7) { c = 0; r++; }
            }
        }
        red[tid] = acc;
    }
    __syncthreads();

    if (tid < 148) {
        int h  = tid / 74;
        int xw = tid - h * 74;
        float t = lg2f(red[tid * 4])     + lg2f(red[tid * 4 + 1])
                + lg2f(red[tid * 4 + 2]) + lg2f(red[tid * 4 + 3]);
        ob[(py0 + h + 3) * 80 + (xw + 3)] = fmaf(t, NEG_LN2_49, ENT_OFF);
    }
    // column borders of the two written rows
    if (tid >= 160 && tid < 172) {
        int k = tid - 160;
        int h = k / 6, j = k - h * 6;
        int col = (j < 3) ? j : (74 + j);      // 0,1,2,77,78,79
        ob[(py0 + h + 3) * 80 + col] = 0.0f;
    }
    // top / bottom border rows
    if (g == 0  && tid < 240) ob[tid] = 0.0f;             // rows 0..2
    if (g == 36 && tid < 240) ob[77 * 80 + tid] = 0.0f;   // rows 77..79
}

// ---------------------------------------------------------------------------
extern "C" void kernel_launch(void* const* d_in, const int* in_sizes, int n_in,
                              void* d_out, int out_size) {
    const float* x = (const float*)d_in[0];
    float* out     = (float*)d_out;

    cudaFuncSetAttribute(entropy_pair_kernel,
                         cudaFuncAttributeMaxDynamicSharedMemorySize, SMEM_BYTES);
    dim3 grid(37, BIMG);               // 148 blocks = 1 per SM
    entropy_pair_kernel<<<grid, BT, SMEM_BYTES>>>(x, out);
}